// round 10
// baseline (speedup 1.0000x reference)
#include <cuda_runtime.h>
#include <math.h>

typedef unsigned long long u64;

// ---------------- fixed shape: P=4, M=N=8192 --------------------------------
#define CAP 65536
#define QCH 1024   // queries per work item (256 thr * 4 qpt)
#define TSL 128    // targets per work item (tile = 4KB); divides 8192
#define NBLK 444   // persistent grid (3 CTAs/SM on 148 SMs)
#define NRED 128

__device__ float    g_tf[8 * 16];
__device__ float    g_cadT[CAP * 8];   // transformed cad, dup fmt [x,x,y,y,z,z,h,h], h=|v|^2/2
__device__ float    g_camT[CAP * 8];   // cam, dup fmt
__device__ float4   g_cadQ[CAP];       // transformed cad, query fmt (x,y,z,|v|^2)
__device__ float4   g_camQ[CAP];
__device__ unsigned g_minbuf[2 * CAP]; // per-(dir,p,query) min d2 as uint bits
__device__ float    g_partial[NRED];
__device__ unsigned g_ticket;

// ---------------- f32x2 helpers ---------------------------------------------
__device__ __forceinline__ u64 pack2(float lo, float hi) {
    u64 r; asm("mov.b64 %0, {%1, %2};" : "=l"(r) : "f"(lo), "f"(hi)); return r;
}

// 4 targets x 1 packed query-pair: 12 FFMA2 + 8 min, fused in one asm scope so
// ptxas can alias the mov.b64 {lo,hi} extractions to register pairs (no MOVs).
__device__ __forceinline__ void quad4(u64 qx, u64 qy, u64 qz,
                                      ulonglong2 a0, ulonglong2 a1,
                                      ulonglong2 b0, ulonglong2 b1,
                                      ulonglong2 c0, ulonglong2 c1,
                                      ulonglong2 d0, ulonglong2 d1,
                                      float& mn0, float& mn1) {
    asm("{\n\t"
        ".reg .b64 tA,tB,tC,tD;\n\t"
        ".reg .f32 l0,l1,l2,l3,h0,h1,h2,h3;\n\t"
        "fma.rn.f32x2 tA, %2, %5, %8;\n\t"    // qx*xx + hh
        "fma.rn.f32x2 tB, %2, %9, %12;\n\t"
        "fma.rn.f32x2 tC, %2, %13, %16;\n\t"
        "fma.rn.f32x2 tD, %2, %17, %20;\n\t"
        "fma.rn.f32x2 tA, %3, %6, tA;\n\t"    // += qy*yy
        "fma.rn.f32x2 tB, %3, %10, tB;\n\t"
        "fma.rn.f32x2 tC, %3, %14, tC;\n\t"
        "fma.rn.f32x2 tD, %3, %18, tD;\n\t"
        "fma.rn.f32x2 tA, %4, %7, tA;\n\t"    // += qz*zz
        "fma.rn.f32x2 tB, %4, %11, tB;\n\t"
        "fma.rn.f32x2 tC, %4, %15, tC;\n\t"
        "fma.rn.f32x2 tD, %4, %19, tD;\n\t"
        "mov.b64 {l0,h0}, tA;\n\t"
        "mov.b64 {l1,h1}, tB;\n\t"
        "mov.b64 {l2,h2}, tC;\n\t"
        "mov.b64 {l3,h3}, tD;\n\t"
        "min.f32 l0, l0, l1;\n\t"
        "min.f32 l2, l2, l3;\n\t"
        "min.f32 h0, h0, h1;\n\t"
        "min.f32 h2, h2, h3;\n\t"
        "min.f32 l0, l0, l2;\n\t"
        "min.f32 h0, h0, h2;\n\t"
        "min.f32 %0, %0, l0;\n\t"
        "min.f32 %1, %1, h0;\n\t"
        "}"
        : "+f"(mn0), "+f"(mn1)
        : "l"(qx), "l"(qy), "l"(qz),
          "l"(a0.x), "l"(a0.y), "l"(a1.x), "l"(a1.y),
          "l"(b0.x), "l"(b0.y), "l"(b1.x), "l"(b1.y),
          "l"(c0.x), "l"(c0.y), "l"(c1.x), "l"(c1.y),
          "l"(d0.x), "l"(d0.y), "l"(d1.x), "l"(d1.y));
}

// ---------------- kernel 1: quat -> transforms ------------------------------
__global__ void k_tf(const float* __restrict__ quat, const float* __restrict__ tra,
                     float* __restrict__ out, int P, int write_out) {
    int p = threadIdx.x;
    if (p >= P) return;
    float a = quat[4 * p + 0], b = quat[4 * p + 1], c = quat[4 * p + 2], d = quat[4 * p + 3];
    float inv = rsqrtf(a * a + b * b + c * c + d * d);
    a *= inv; b *= inv; c *= inv; d *= inv;
    float tf[16];
    tf[0]  = 1.f - 2.f * (c * c + d * d);
    tf[1]  = 2.f * (b * c - a * d);
    tf[2]  = 2.f * (a * c + b * d);
    tf[3]  = tra[3 * p + 0];
    tf[4]  = 2.f * (b * c + a * d);
    tf[5]  = 1.f - 2.f * (b * b + d * d);
    tf[6]  = 2.f * (c * d - a * b);
    tf[7]  = tra[3 * p + 1];
    tf[8]  = 2.f * (b * d - a * c);
    tf[9]  = 2.f * (a * b + c * d);
    tf[10] = 1.f - 2.f * (b * b + c * c);
    tf[11] = tra[3 * p + 2];
    tf[12] = 0.f; tf[13] = 0.f; tf[14] = 0.f; tf[15] = 1.f;
#pragma unroll
    for (int i = 0; i < 16; i++) {
        g_tf[p * 16 + i] = tf[i];
        if (write_out) out[1 + p * 16 + i] = tf[i];
    }
}

// ---------------- kernel 2: prepare point buffers + init minbuf -------------
__global__ void k_prep(const float* __restrict__ cad, const float* __restrict__ cam,
                       int P, int M, int N, int total) {
    int idx = blockIdx.x * blockDim.x + threadIdx.x;
    if (idx >= total) return;
    g_minbuf[idx] = 0x7f800000u;  // +inf

    float vx, vy, vz;
    if (idx < P * M) {
        int p = idx / M;
        const float* pt = cad + (size_t)idx * 3;
        const float* tf = g_tf + p * 16;
        float x = pt[0], y = pt[1], z = pt[2];
        vx = tf[0] * x + tf[1] * y + tf[2]  * z + tf[3];
        vy = tf[4] * x + tf[5] * y + tf[6]  * z + tf[7];
        vz = tf[8] * x + tf[9] * y + tf[10] * z + tf[11];
        float n2 = vx * vx + vy * vy + vz * vz;
        float* T = g_cadT + (size_t)idx * 8;
        T[0] = vx; T[1] = vx; T[2] = vy; T[3] = vy;
        T[4] = vz; T[5] = vz; T[6] = 0.5f * n2; T[7] = 0.5f * n2;
        g_cadQ[idx] = make_float4(vx, vy, vz, n2);
    } else {
        int j = idx - P * M;
        const float* pt = cam + (size_t)j * 3;
        vx = pt[0]; vy = pt[1]; vz = pt[2];
        float n2 = vx * vx + vy * vy + vz * vz;
        float* T = g_camT + (size_t)j * 8;
        T[0] = vx; T[1] = vx; T[2] = vy; T[3] = vy;
        T[4] = vz; T[5] = vz; T[6] = 0.5f * n2; T[7] = 0.5f * n2;
        g_camQ[j] = make_float4(vx, vy, vz, n2);
    }
}

// ---------------- kernel 2.5: reset ticket (aligns ncu on offset 3) ---------
__global__ void k_tick() {
    if (threadIdx.x == 0) g_ticket = 0u;
}

// ---------------- kernel 3: chamfer (hot; persistent + work stealing) -------
__global__ void __launch_bounds__(256, 3) k_chamfer(int P, int M, int N,
                                                    int qcA, int tsA, int qcB, int tsB) {
    __shared__ __align__(16) float tile[TSL * 8];
    __shared__ int s_item;

    const int tid = threadIdx.x;
    const float INF = __int_as_float(0x7f800000);
    const int itemsA = P * qcA * tsA;
    const int itemsB = P * qcB * tsB;
    const int totalItems = itemsA + itemsB;

    for (;;) {
        __syncthreads();            // prev iter fully done with tile & s_item
        if (tid == 0) s_item = (int)atomicAdd(&g_ticket, 1u);
        __syncthreads();
        int item = s_item;
        if (item >= totalItems) break;

        int p, qc, sl, minoff;
        const float4* Q;
        const float*  T;
        if (item < itemsA) {
            p = item / (qcA * tsA); int r = item % (qcA * tsA); qc = r / tsA; sl = r % tsA;
            Q = g_cadQ + (size_t)p * M;
            T = g_camT + (size_t)p * N * 8;
            minoff = p * M;
        } else {
            int b1 = item - itemsA;
            p = b1 / (qcB * tsB); int r = b1 % (qcB * tsB); qc = r / tsB; sl = r % tsB;
            Q = g_camQ + (size_t)p * N;
            T = g_cadT + (size_t)p * M * 8;
            minoff = P * M + p * N;
        }

        // ---- 4 query points per thread (2 packed pairs); no bounds checks ----
        u64 qnx[2], qny[2], qnz[2];
        float mn0[2], mn1[2], x2a[2], x2b[2];
        int base = qc * QCH + tid;
#pragma unroll
        for (int k = 0; k < 2; k++) {
            float4 A = Q[base + (2 * k) * 256];
            float4 B = Q[base + (2 * k + 1) * 256];
            qnx[k] = pack2(-A.x, -B.x);
            qny[k] = pack2(-A.y, -B.y);
            qnz[k] = pack2(-A.z, -B.z);
            x2a[k] = A.w; x2b[k] = B.w;
            mn0[k] = INF; mn1[k] = INF;
        }

        // ---- cooperative tile load: 256 float4 = full 4KB ----
        ((float4*)tile)[tid] = ((const float4*)(T + (size_t)sl * TSL * 8))[tid];
        __syncthreads();

        // ---- main loop: 4 targets x 4 queries per iteration ----
#pragma unroll 2
        for (int j = 0; j < TSL; j += 4) {
            const float* tp = tile + j * 8;
            ulonglong2 a0 = *(const ulonglong2*)(tp);
            ulonglong2 a1 = *(const ulonglong2*)(tp + 4);
            ulonglong2 b0 = *(const ulonglong2*)(tp + 8);
            ulonglong2 b1 = *(const ulonglong2*)(tp + 12);
            ulonglong2 c0 = *(const ulonglong2*)(tp + 16);
            ulonglong2 c1 = *(const ulonglong2*)(tp + 20);
            ulonglong2 d0 = *(const ulonglong2*)(tp + 24);
            ulonglong2 d1 = *(const ulonglong2*)(tp + 28);
#pragma unroll
            for (int k = 0; k < 2; k++) {
                quad4(qnx[k], qny[k], qnz[k],
                      a0, a1, b0, b1, c0, c1, d0, d1,
                      mn0[k], mn1[k]);
            }
        }

        // ---- combine across slices: d2 = 2*g + |q|^2 (>=0), bitwise uint min ----
#pragma unroll
        for (int k = 0; k < 2; k++) {
            float da = fmaxf(fmaf(2.f, mn0[k], x2a[k]), 0.f);
            float db = fmaxf(fmaf(2.f, mn1[k], x2b[k]), 0.f);
            atomicMin(g_minbuf + minoff + base + (2 * k) * 256,     __float_as_uint(da));
            atomicMin(g_minbuf + minoff + base + (2 * k + 1) * 256, __float_as_uint(db));
        }
    }
}

// ---------------- kernel 4: weighted sqrt-sum partials -----------------------
__global__ void k_red(const float* __restrict__ w, int P, int M, int N) {
    __shared__ float sh[256];
    int total = P * (M + N);
    float s = 0.f;
    for (int e = blockIdx.x * 256 + threadIdx.x; e < total; e += NRED * 256) {
        int p; float invc;
        if (e < P * M) { p = e / M; invc = 1.0f / (float)M; }
        else           { p = (e - P * M) / N; invc = 1.0f / (float)N; }
        s += w[p] * invc * sqrtf(__uint_as_float(g_minbuf[e]));
    }
    sh[threadIdx.x] = s;
    __syncthreads();
    for (int o = 128; o > 0; o >>= 1) {
        if (threadIdx.x < o) sh[threadIdx.x] += sh[threadIdx.x + o];
        __syncthreads();
    }
    if (threadIdx.x == 0) g_partial[blockIdx.x] = sh[0];
}

// ---------------- kernel 5: deterministic final sum --------------------------
__global__ void k_fin(float* __restrict__ out) {
    if (threadIdx.x == 0) {
        float s = 0.f;
        for (int i = 0; i < NRED; i++) s += g_partial[i];
        out[0] = s;
    }
}

// ---------------- launcher ----------------------------------------------------
extern "C" void kernel_launch(void* const* d_in, const int* in_sizes, int n_in,
                              void* d_out, int out_size) {
    const float* cam  = (const float*)d_in[0];  // (P,N,3)
    const float* cad  = (const float*)d_in[1];  // (P,M,3)
    const float* wgt  = (const float*)d_in[2];  // (P,)
    const float* quat = (const float*)d_in[3];  // (P,4)
    const float* tra  = (const float*)d_in[4];  // (P,3,1)
    float* out = (float*)d_out;

    int P = in_sizes[2];
    int N = in_sizes[0] / (3 * P);
    int M = in_sizes[1] / (3 * P);
    int write_out = (out_size >= 1 + 16 * P) ? 1 : 0;

    k_tf<<<1, 32>>>(quat, tra, out, P, write_out);                   // launch 0

    int total = P * (M + N);
    k_prep<<<(total + 255) / 256, 256>>>(cad, cam, P, M, N, total);  // launch 1

    k_tick<<<1, 32>>>();                                             // launch 2

    int qcA = (M + QCH - 1) / QCH, tsA = (N + TSL - 1) / TSL;
    int qcB = (N + QCH - 1) / QCH, tsB = (M + TSL - 1) / TSL;
    k_chamfer<<<NBLK, 256>>>(P, M, N, qcA, tsA, qcB, tsB);           // launch 3 (hot)

    k_red<<<NRED, 256>>>(wgt, P, M, N);                              // launch 4
    k_fin<<<1, 1>>>(out);                                            // launch 5
}

// round 11
// speedup vs baseline: 1.0165x; 1.0165x over previous
#include <cuda_runtime.h>
#include <math.h>

typedef unsigned long long u64;
typedef unsigned int u32;

// ---------------- fixed shape: P=4, M=N=8192 --------------------------------
#define CAP 65536
#define QCH 2048   // queries per work item (256 thr * 8 qpt)
#define TSL 128    // targets per work item (tile = 4KB); divides 8192
#define NBLK 444   // persistent grid (3 CTAs/SM on 148 SMs)
#define NRED 256

__device__ float    g_cadT[CAP * 8];   // transformed cad, dup fmt [x,x,y,y,z,z,h,h], h=|v|^2/2
__device__ float    g_camT[CAP * 8];   // cam, dup fmt
__device__ float4   g_cadQ[CAP];       // transformed cad, query fmt (x,y,z,|v|^2)
__device__ float4   g_camQ[CAP];
__device__ unsigned g_minbuf[2 * CAP]; // per-(dir,p,query) min d2 as uint bits
__device__ float    g_partial[NRED];
__device__ unsigned g_ticket;

// ---------------- f32x2 helpers ---------------------------------------------
__device__ __forceinline__ u64 pack2(float lo, float hi) {
    u64 r; asm("mov.b64 %0, {%1, %2};" : "=l"(r) : "f"(lo), "f"(hi)); return r;
}
__device__ __forceinline__ void unpack2(u64 v, float& lo, float& hi) {
    asm("mov.b64 {%0, %1}, %2;" : "=f"(lo), "=f"(hi) : "l"(v));
}
__device__ __forceinline__ u64 fma2(u64 a, u64 b, u64 c) {
    u64 d; asm("fma.rn.f32x2 %0, %1, %2, %3;" : "=l"(d) : "l"(a), "l"(b), "l"(c)); return d;
}

// ---------------- cp.async helpers -------------------------------------------
__device__ __forceinline__ void cp16(u32 dst_smem, const void* src) {
    asm volatile("cp.async.cg.shared.global [%0], [%1], 16;" :: "r"(dst_smem), "l"(src));
}
__device__ __forceinline__ void cp_commit() {
    asm volatile("cp.async.commit_group;");
}
__device__ __forceinline__ void cp_wait0() {
    asm volatile("cp.async.wait_group 0;");
}

// ---------------- transform builder ------------------------------------------
__device__ __forceinline__ void make_tf(const float* quat, const float* tra, int p, float tf[12]) {
    float a = quat[4*p], b = quat[4*p+1], c = quat[4*p+2], d = quat[4*p+3];
    float inv = rsqrtf(a*a + b*b + c*c + d*d);
    a *= inv; b *= inv; c *= inv; d *= inv;
    tf[0] = 1.f - 2.f*(c*c + d*d); tf[1] = 2.f*(b*c - a*d);        tf[2]  = 2.f*(a*c + b*d);        tf[3]  = tra[3*p+0];
    tf[4] = 2.f*(b*c + a*d);       tf[5] = 1.f - 2.f*(b*b + d*d);  tf[6]  = 2.f*(c*d - a*b);        tf[7]  = tra[3*p+1];
    tf[8] = 2.f*(b*d - a*c);       tf[9] = 2.f*(a*b + c*d);        tf[10] = 1.f - 2.f*(b*b + c*c);  tf[11] = tra[3*p+2];
}

// ---------------- launch 0: transforms + point buffers + minbuf + ticket ----
__global__ void k_prep(const float* __restrict__ cad, const float* __restrict__ cam,
                       const float* __restrict__ quat, const float* __restrict__ tra,
                       float* __restrict__ out, int P, int M, int N, int total, int write_out) {
    int idx = blockIdx.x * blockDim.x + threadIdx.x;
    if (idx == 0) g_ticket = 0u;
    if (blockIdx.x == 0 && threadIdx.x < P && write_out) {
        float tf[12]; make_tf(quat, tra, threadIdx.x, tf);
        float* o = out + 1 + threadIdx.x * 16;
#pragma unroll
        for (int i = 0; i < 12; i++) o[i] = tf[i];
        o[12] = 0.f; o[13] = 0.f; o[14] = 0.f; o[15] = 1.f;
    }
    if (idx >= total) return;
    g_minbuf[idx] = 0x7f800000u;  // +inf

    float vx, vy, vz;
    if (idx < P * M) {
        int p = idx / M;
        float tf[12]; make_tf(quat, tra, p, tf);
        const float* pt = cad + (size_t)idx * 3;
        float x = pt[0], y = pt[1], z = pt[2];
        vx = tf[0]*x + tf[1]*y + tf[2]*z  + tf[3];
        vy = tf[4]*x + tf[5]*y + tf[6]*z  + tf[7];
        vz = tf[8]*x + tf[9]*y + tf[10]*z + tf[11];
        float n2 = vx*vx + vy*vy + vz*vz;
        float* T = g_cadT + (size_t)idx * 8;
        T[0] = vx; T[1] = vx; T[2] = vy; T[3] = vy;
        T[4] = vz; T[5] = vz; T[6] = 0.5f * n2; T[7] = 0.5f * n2;
        g_cadQ[idx] = make_float4(vx, vy, vz, n2);
    } else {
        int j = idx - P * M;
        const float* pt = cam + (size_t)j * 3;
        vx = pt[0]; vy = pt[1]; vz = pt[2];
        float n2 = vx*vx + vy*vy + vz*vz;
        float* T = g_camT + (size_t)j * 8;
        T[0] = vx; T[1] = vx; T[2] = vy; T[3] = vy;
        T[4] = vz; T[5] = vz; T[6] = 0.5f * n2; T[7] = 0.5f * n2;
        g_camQ[j] = make_float4(vx, vy, vz, n2);
    }
}

// ---------------- item decode -------------------------------------------------
__device__ __forceinline__ void decode_item(int item, int P, int M, int N,
                                            int qcA, int tsA, int qcB, int tsB, int itemsA,
                                            const float4*& Q, const float*& Tsrc, int& minoff, int& qbase) {
    int p, qc, sl;
    if (item < itemsA) {
        p = item / (qcA * tsA); int r = item % (qcA * tsA); qc = r / tsA; sl = r % tsA;
        Q = g_cadQ + (size_t)p * M;
        Tsrc = g_camT + ((size_t)p * N + (size_t)sl * TSL) * 8;
        minoff = p * M;
    } else {
        int b1 = item - itemsA;
        p = b1 / (qcB * tsB); int r = b1 % (qcB * tsB); qc = r / tsB; sl = r % tsB;
        Q = g_camQ + (size_t)p * N;
        Tsrc = g_cadT + ((size_t)p * M + (size_t)sl * TSL) * 8;
        minoff = P * M + p * N;
    }
    qbase = qc * QCH;
}

// ---------------- launch 1 (hot): chamfer, double-buffered cp.async ---------
__global__ void __launch_bounds__(256, 3) k_chamfer(int P, int M, int N,
                                                    int qcA, int tsA, int qcB, int tsB) {
    __shared__ __align__(16) float tile[2][TSL * 8];   // 2 x 4KB
    __shared__ int s_item[2];

    const int tid = threadIdx.x;
    const float INF = __int_as_float(0x7f800000);
    const int itemsA = P * qcA * tsA;
    const int totalItems = itemsA + P * qcB * tsB;

    // ---- prologue: ticket 0 + async copy into buffer 0 ----
    if (tid == 0) s_item[0] = (int)atomicAdd(&g_ticket, 1u);
    __syncthreads();
    int cur = 0;
    int item = s_item[0];
    if (item < totalItems) {
        const float4* Q; const float* Tsrc; int minoff, qbase;
        decode_item(item, P, M, N, qcA, tsA, qcB, tsB, itemsA, Q, Tsrc, minoff, qbase);
        cp16((u32)__cvta_generic_to_shared(&tile[0][tid * 4]), Tsrc + tid * 4);
        cp_commit();
    }

    while (item < totalItems) {
        // fetch NEXT ticket while this item's tile copy is in flight
        if (tid == 0) s_item[cur ^ 1] = (int)atomicAdd(&g_ticket, 1u);

        const float4* Q; const float* Tsrc; int minoff, qbase;
        decode_item(item, P, M, N, qcA, tsA, qcB, tsB, itemsA, Q, Tsrc, minoff, qbase);

        // ---- load this thread's 8 query points (overlaps with cp.async) ----
        u64 qnx[4], qny[4], qnz[4];
        float mn0[4], mn1[4], x2a[4], x2b[4];
        int base = qbase + tid;
#pragma unroll
        for (int k = 0; k < 4; k++) {
            float4 A = Q[base + (2 * k) * 256];
            float4 B = Q[base + (2 * k + 1) * 256];
            qnx[k] = pack2(-A.x, -B.x);
            qny[k] = pack2(-A.y, -B.y);
            qnz[k] = pack2(-A.z, -B.z);
            x2a[k] = A.w; x2b[k] = B.w;
            mn0[k] = INF; mn1[k] = INF;
        }

        // ---- tile[cur] ready + s_item[next] visible ----
        cp_wait0();
        __syncthreads();

        // ---- kick the NEXT item's tile copy into the other buffer ----
        int nxt = s_item[cur ^ 1];
        if (nxt < totalItems) {
            const float4* Qn; const float* Tn; int mo, qb;
            decode_item(nxt, P, M, N, qcA, tsA, qcB, tsB, itemsA, Qn, Tn, mo, qb);
            cp16((u32)__cvta_generic_to_shared(&tile[cur ^ 1][tid * 4]), Tn + tid * 4);
            cp_commit();
        }

        // ---- main loop: 4 targets x 8 queries per iteration ----
        const float* tb = tile[cur];
#pragma unroll 2
        for (int j = 0; j < TSL; j += 4) {
            const float* tp = tb + j * 8;
            ulonglong2 a0 = *(const ulonglong2*)(tp);
            ulonglong2 a1 = *(const ulonglong2*)(tp + 4);
            ulonglong2 b0 = *(const ulonglong2*)(tp + 8);
            ulonglong2 b1 = *(const ulonglong2*)(tp + 12);
            ulonglong2 c0 = *(const ulonglong2*)(tp + 16);
            ulonglong2 c1 = *(const ulonglong2*)(tp + 20);
            ulonglong2 d0 = *(const ulonglong2*)(tp + 24);
            ulonglong2 d1 = *(const ulonglong2*)(tp + 28);
#pragma unroll
            for (int k = 0; k < 4; k++) {
                u64 gA = fma2(qnx[k], a0.x, a1.y);
                u64 gB = fma2(qnx[k], b0.x, b1.y);
                u64 gC = fma2(qnx[k], c0.x, c1.y);
                u64 gD = fma2(qnx[k], d0.x, d1.y);
                gA = fma2(qny[k], a0.y, gA);
                gB = fma2(qny[k], b0.y, gB);
                gC = fma2(qny[k], c0.y, gC);
                gD = fma2(qny[k], d0.y, gD);
                gA = fma2(qnz[k], a1.x, gA);
                gB = fma2(qnz[k], b1.x, gB);
                gC = fma2(qnz[k], c1.x, gC);
                gD = fma2(qnz[k], d1.x, gD);
                float alo, ahi, blo, bhi, clo, chi, dlo, dhi;
                unpack2(gA, alo, ahi); unpack2(gB, blo, bhi);
                unpack2(gC, clo, chi); unpack2(gD, dlo, dhi);
                float lo01 = fminf(alo, blo), lo23 = fminf(clo, dlo);
                float hi01 = fminf(ahi, bhi), hi23 = fminf(chi, dhi);
                mn0[k] = fminf(mn0[k], fminf(lo01, lo23));
                mn1[k] = fminf(mn1[k], fminf(hi01, hi23));
            }
        }

        // ---- combine across slices: d2 = 2*g + |q|^2 (>=0), bitwise uint min ----
#pragma unroll
        for (int k = 0; k < 4; k++) {
            float da = fmaxf(fmaf(2.f, mn0[k], x2a[k]), 0.f);
            float db = fmaxf(fmaf(2.f, mn1[k], x2b[k]), 0.f);
            atomicMin(g_minbuf + minoff + base + (2 * k) * 256,     __float_as_uint(da));
            atomicMin(g_minbuf + minoff + base + (2 * k + 1) * 256, __float_as_uint(db));
        }

        cur ^= 1;
        item = nxt;
        __syncthreads();   // all reads of old buffer done before its next overwrite
    }
}

// ---------------- launch 2: weighted sqrt-sum partials ----------------------
__global__ void k_red(const float* __restrict__ w, int P, int M, int N) {
    __shared__ float sh[256];
    int total = P * (M + N);
    float s = 0.f;
    for (int e = blockIdx.x * 256 + threadIdx.x; e < total; e += NRED * 256) {
        int p; float invc;
        if (e < P * M) { p = e / M; invc = 1.0f / (float)M; }
        else           { p = (e - P * M) / N; invc = 1.0f / (float)N; }
        s += w[p] * invc * sqrtf(__uint_as_float(g_minbuf[e]));
    }
    sh[threadIdx.x] = s;
    __syncthreads();
    for (int o = 128; o > 0; o >>= 1) {
        if (threadIdx.x < o) sh[threadIdx.x] += sh[threadIdx.x + o];
        __syncthreads();
    }
    if (threadIdx.x == 0) g_partial[blockIdx.x] = sh[0];
}

// ---------------- launch 3: deterministic final sum --------------------------
__global__ void k_fin(float* __restrict__ out) {
    if (threadIdx.x == 0) {
        float s = 0.f;
        for (int i = 0; i < NRED; i++) s += g_partial[i];
        out[0] = s;
    }
}

// ---------------- launcher ----------------------------------------------------
extern "C" void kernel_launch(void* const* d_in, const int* in_sizes, int n_in,
                              void* d_out, int out_size) {
    const float* cam  = (const float*)d_in[0];  // (P,N,3)
    const float* cad  = (const float*)d_in[1];  // (P,M,3)
    const float* wgt  = (const float*)d_in[2];  // (P,)
    const float* quat = (const float*)d_in[3];  // (P,4)
    const float* tra  = (const float*)d_in[4];  // (P,3,1)
    float* out = (float*)d_out;

    int P = in_sizes[2];
    int N = in_sizes[0] / (3 * P);
    int M = in_sizes[1] / (3 * P);
    int write_out = (out_size >= 1 + 16 * P) ? 1 : 0;

    int total = P * (M + N);
    k_prep<<<(total + 255) / 256, 256>>>(cad, cam, quat, tra, out, P, M, N, total, write_out); // 0

    int qcA = (M + QCH - 1) / QCH, tsA = (N + TSL - 1) / TSL;
    int qcB = (N + QCH - 1) / QCH, tsB = (M + TSL - 1) / TSL;
    k_chamfer<<<NBLK, 256>>>(P, M, N, qcA, tsA, qcB, tsB);                                     // 1 (hot)

    k_red<<<NRED, 256>>>(wgt, P, M, N);                                                        // 2
    k_fin<<<1, 1>>>(out);                                                                      // 3
}

// round 12
// speedup vs baseline: 1.4792x; 1.4552x over previous
#include <cuda_runtime.h>
#include <math.h>

typedef unsigned long long u64;
typedef unsigned int u32;

// ---------------- fixed shape: P=4, M=N=8192 --------------------------------
#define CAP 65536
#define QCH 2048   // queries per block (256 thr * 8 qpt)
#define TSL 128    // targets per block (tile = 4KB); divides 8192
#define NRED 128

__device__ float    g_cadT[CAP * 8];   // transformed cad, dup fmt [x,x,y,y,z,z,h,h], h=|v|^2/2
__device__ float    g_camT[CAP * 8];   // cam, dup fmt
__device__ float4   g_cadQ[CAP];       // transformed cad, query fmt (x,y,z,|v|^2)
__device__ float4   g_camQ[CAP];
__device__ unsigned g_minbuf[2 * CAP]; // per-(dir,p,query) min d2 as uint bits
__device__ float    g_partial[NRED];

// ---------------- f32x2 helpers ---------------------------------------------
__device__ __forceinline__ u64 pack2(float lo, float hi) {
    u64 r; asm("mov.b64 %0, {%1, %2};" : "=l"(r) : "f"(lo), "f"(hi)); return r;
}
__device__ __forceinline__ void unpack2(u64 v, float& lo, float& hi) {
    asm("mov.b64 {%0, %1}, %2;" : "=f"(lo), "=f"(hi) : "l"(v));
}
__device__ __forceinline__ u64 fma2(u64 a, u64 b, u64 c) {
    u64 d; asm("fma.rn.f32x2 %0, %1, %2, %3;" : "=l"(d) : "l"(a), "l"(b), "l"(c)); return d;
}

// ---------------- transform builder ------------------------------------------
__device__ __forceinline__ void make_tf(const float* quat, const float* tra, int p, float tf[12]) {
    float a = quat[4*p], b = quat[4*p+1], c = quat[4*p+2], d = quat[4*p+3];
    float inv = rsqrtf(a*a + b*b + c*c + d*d);
    a *= inv; b *= inv; c *= inv; d *= inv;
    tf[0] = 1.f - 2.f*(c*c + d*d); tf[1] = 2.f*(b*c - a*d);        tf[2]  = 2.f*(a*c + b*d);        tf[3]  = tra[3*p+0];
    tf[4] = 2.f*(b*c + a*d);       tf[5] = 1.f - 2.f*(b*b + d*d);  tf[6]  = 2.f*(c*d - a*b);        tf[7]  = tra[3*p+1];
    tf[8] = 2.f*(b*d - a*c);       tf[9] = 2.f*(a*b + c*d);        tf[10] = 1.f - 2.f*(b*b + c*c);  tf[11] = tra[3*p+2];
}

// ---------------- launch 0: transforms + point buffers + minbuf -------------
__global__ void k_prep(const float* __restrict__ cad, const float* __restrict__ cam,
                       const float* __restrict__ quat, const float* __restrict__ tra,
                       float* __restrict__ out, int P, int M, int N, int total, int write_out) {
    int idx = blockIdx.x * blockDim.x + threadIdx.x;
    if (blockIdx.x == 0 && threadIdx.x < P && write_out) {
        float tf[12]; make_tf(quat, tra, threadIdx.x, tf);
        float* o = out + 1 + threadIdx.x * 16;
#pragma unroll
        for (int i = 0; i < 12; i++) o[i] = tf[i];
        o[12] = 0.f; o[13] = 0.f; o[14] = 0.f; o[15] = 1.f;
    }
    if (idx >= total) return;
    g_minbuf[idx] = 0x7f800000u;  // +inf

    float vx, vy, vz;
    if (idx < P * M) {
        int p = idx / M;
        float tf[12]; make_tf(quat, tra, p, tf);
        const float* pt = cad + (size_t)idx * 3;
        float x = pt[0], y = pt[1], z = pt[2];
        vx = tf[0]*x + tf[1]*y + tf[2]*z  + tf[3];
        vy = tf[4]*x + tf[5]*y + tf[6]*z  + tf[7];
        vz = tf[8]*x + tf[9]*y + tf[10]*z + tf[11];
        float n2 = vx*vx + vy*vy + vz*vz;
        float* T = g_cadT + (size_t)idx * 8;
        T[0] = vx; T[1] = vx; T[2] = vy; T[3] = vy;
        T[4] = vz; T[5] = vz; T[6] = 0.5f * n2; T[7] = 0.5f * n2;
        g_cadQ[idx] = make_float4(vx, vy, vz, n2);
    } else {
        int j = idx - P * M;
        const float* pt = cam + (size_t)j * 3;
        vx = pt[0]; vy = pt[1]; vz = pt[2];
        float n2 = vx*vx + vy*vy + vz*vz;
        float* T = g_camT + (size_t)j * 8;
        T[0] = vx; T[1] = vx; T[2] = vy; T[3] = vy;
        T[4] = vz; T[5] = vz; T[6] = 0.5f * n2; T[7] = 0.5f * n2;
        g_camQ[j] = make_float4(vx, vy, vz, n2);
    }
}

// ---------------- launch 1 (hot): chamfer, one item per block ---------------
__global__ void __launch_bounds__(256, 3) k_chamfer(int P, int M, int N,
                                                    int qcA, int tsA, int qcB, int tsB) {
    __shared__ __align__(16) float tile[TSL * 8];

    const int tid = threadIdx.x;
    const float INF = __int_as_float(0x7f800000);
    const int itemsA = P * qcA * tsA;
    const int item = blockIdx.x;

    int p, qc, sl, minoff;
    const float4* Q;
    const float*  T;
    if (item < itemsA) {
        p = item / (qcA * tsA); int r = item % (qcA * tsA); qc = r / tsA; sl = r % tsA;
        Q = g_cadQ + (size_t)p * M;
        T = g_camT + (size_t)p * N * 8;
        minoff = p * M;
    } else {
        int b1 = item - itemsA;
        p = b1 / (qcB * tsB); int r = b1 % (qcB * tsB); qc = r / tsB; sl = r % tsB;
        Q = g_camQ + (size_t)p * N;
        T = g_cadT + (size_t)p * M * 8;
        minoff = P * M + p * N;
    }

    // ---- cooperative tile load: 256 float4 = full 4KB ----
    ((float4*)tile)[tid] = ((const float4*)(T + (size_t)sl * TSL * 8))[tid];

    // ---- 8 query points per thread (4 packed pairs); no bounds checks ----
    u64 qnx[4], qny[4], qnz[4];
    float mn0[4], mn1[4], x2a[4], x2b[4];
    int base = qc * QCH + tid;
#pragma unroll
    for (int k = 0; k < 4; k++) {
        float4 A = Q[base + (2 * k) * 256];
        float4 B = Q[base + (2 * k + 1) * 256];
        qnx[k] = pack2(-A.x, -B.x);
        qny[k] = pack2(-A.y, -B.y);
        qnz[k] = pack2(-A.z, -B.z);
        x2a[k] = A.w; x2b[k] = B.w;
        mn0[k] = INF; mn1[k] = INF;
    }
    __syncthreads();

    // ---- main loop: 4 targets x 8 queries per iteration ----
#pragma unroll 2
    for (int j = 0; j < TSL; j += 4) {
        const float* tp = tile + j * 8;
        ulonglong2 a0 = *(const ulonglong2*)(tp);
        ulonglong2 a1 = *(const ulonglong2*)(tp + 4);
        ulonglong2 b0 = *(const ulonglong2*)(tp + 8);
        ulonglong2 b1 = *(const ulonglong2*)(tp + 12);
        ulonglong2 c0 = *(const ulonglong2*)(tp + 16);
        ulonglong2 c1 = *(const ulonglong2*)(tp + 20);
        ulonglong2 d0 = *(const ulonglong2*)(tp + 24);
        ulonglong2 d1 = *(const ulonglong2*)(tp + 28);
#pragma unroll
        for (int k = 0; k < 4; k++) {
            u64 gA = fma2(qnx[k], a0.x, a1.y);
            u64 gB = fma2(qnx[k], b0.x, b1.y);
            u64 gC = fma2(qnx[k], c0.x, c1.y);
            u64 gD = fma2(qnx[k], d0.x, d1.y);
            gA = fma2(qny[k], a0.y, gA);
            gB = fma2(qny[k], b0.y, gB);
            gC = fma2(qny[k], c0.y, gC);
            gD = fma2(qny[k], d0.y, gD);
            gA = fma2(qnz[k], a1.x, gA);
            gB = fma2(qnz[k], b1.x, gB);
            gC = fma2(qnz[k], c1.x, gC);
            gD = fma2(qnz[k], d1.x, gD);
            float alo, ahi, blo, bhi, clo, chi, dlo, dhi;
            unpack2(gA, alo, ahi); unpack2(gB, blo, bhi);
            unpack2(gC, clo, chi); unpack2(gD, dlo, dhi);
            float lo01 = fminf(alo, blo), lo23 = fminf(clo, dlo);
            float hi01 = fminf(ahi, bhi), hi23 = fminf(chi, dhi);
            mn0[k] = fminf(mn0[k], fminf(lo01, lo23));
            mn1[k] = fminf(mn1[k], fminf(hi01, hi23));
        }
    }

    // ---- combine across slices: d2 = 2*g + |q|^2 (>=0), bitwise uint min ----
#pragma unroll
    for (int k = 0; k < 4; k++) {
        float da = fmaxf(fmaf(2.f, mn0[k], x2a[k]), 0.f);
        float db = fmaxf(fmaf(2.f, mn1[k], x2b[k]), 0.f);
        atomicMin(g_minbuf + minoff + base + (2 * k) * 256,     __float_as_uint(da));
        atomicMin(g_minbuf + minoff + base + (2 * k + 1) * 256, __float_as_uint(db));
    }
}

// ---------------- launch 2: weighted sqrt-sum partials ----------------------
__global__ void k_red(const float* __restrict__ w, int P, int M, int N) {
    __shared__ float sh[256];
    int total = P * (M + N);
    float s = 0.f;
    for (int e = blockIdx.x * 256 + threadIdx.x; e < total; e += NRED * 256) {
        int p; float invc;
        if (e < P * M) { p = e / M; invc = 1.0f / (float)M; }
        else           { p = (e - P * M) / N; invc = 1.0f / (float)N; }
        s += w[p] * invc * sqrtf(__uint_as_float(g_minbuf[e]));
    }
    sh[threadIdx.x] = s;
    __syncthreads();
    for (int o = 128; o > 0; o >>= 1) {
        if (threadIdx.x < o) sh[threadIdx.x] += sh[threadIdx.x + o];
        __syncthreads();
    }
    if (threadIdx.x == 0) g_partial[blockIdx.x] = sh[0];
}

// ---------------- launch 3: parallel deterministic final sum ----------------
__global__ void k_fin(float* __restrict__ out) {
    __shared__ float sh[NRED];
    int tid = threadIdx.x;
    sh[tid] = g_partial[tid];
    __syncthreads();
    for (int o = NRED / 2; o > 0; o >>= 1) {
        if (tid < o) sh[tid] += sh[tid + o];
        __syncthreads();
    }
    if (tid == 0) out[0] = sh[0];
}

// ---------------- launcher ----------------------------------------------------
extern "C" void kernel_launch(void* const* d_in, const int* in_sizes, int n_in,
                              void* d_out, int out_size) {
    const float* cam  = (const float*)d_in[0];  // (P,N,3)
    const float* cad  = (const float*)d_in[1];  // (P,M,3)
    const float* wgt  = (const float*)d_in[2];  // (P,)
    const float* quat = (const float*)d_in[3];  // (P,4)
    const float* tra  = (const float*)d_in[4];  // (P,3,1)
    float* out = (float*)d_out;

    int P = in_sizes[2];
    int N = in_sizes[0] / (3 * P);
    int M = in_sizes[1] / (3 * P);
    int write_out = (out_size >= 1 + 16 * P) ? 1 : 0;

    int total = P * (M + N);
    k_prep<<<(total + 255) / 256, 256>>>(cad, cam, quat, tra, out, P, M, N, total, write_out); // 0

    int qcA = (M + QCH - 1) / QCH, tsA = (N + TSL - 1) / TSL;
    int qcB = (N + QCH - 1) / QCH, tsB = (M + TSL - 1) / TSL;
    int items = P * (qcA * tsA + qcB * tsB);   // 2048
    k_chamfer<<<items, 256>>>(P, M, N, qcA, tsA, qcB, tsB);                                    // 1 (hot)

    k_red<<<NRED, 256>>>(wgt, P, M, N);                                                        // 2
    k_fin<<<1, NRED>>>(out);                                                                   // 3
}

// round 13
// speedup vs baseline: 1.5068x; 1.0187x over previous
#include <cuda_runtime.h>
#include <math.h>

typedef unsigned long long u64;
typedef unsigned int u32;

// ---------------- fixed shape: P=4, M=N=8192 --------------------------------
#define CAP 65536
#define QCH 1024   // queries per block (256 thr * 4 qpt)
#define TSL 128    // targets per block (tile = 4KB); divides 8192
#define NRED 128

__device__ float    g_cadT[CAP * 8];   // transformed cad, dup fmt [x,x,y,y,z,z,h,h], h=|v|^2/2
__device__ float    g_camT[CAP * 8];   // cam, dup fmt
__device__ float4   g_cadQ[CAP];       // transformed cad, query fmt (x,y,z,|v|^2)
__device__ float4   g_camQ[CAP];
__device__ unsigned g_minbuf[2 * CAP]; // per-(dir,p,query) min d2 as uint bits
__device__ float    g_partial[NRED];
__device__ unsigned g_done;

// ---------------- f32x2 helpers ---------------------------------------------
__device__ __forceinline__ u64 pack2(float lo, float hi) {
    u64 r; asm("mov.b64 %0, {%1, %2};" : "=l"(r) : "f"(lo), "f"(hi)); return r;
}
__device__ __forceinline__ void unpack2(u64 v, float& lo, float& hi) {
    asm("mov.b64 {%0, %1}, %2;" : "=f"(lo), "=f"(hi) : "l"(v));
}
__device__ __forceinline__ u64 fma2(u64 a, u64 b, u64 c) {
    u64 d; asm("fma.rn.f32x2 %0, %1, %2, %3;" : "=l"(d) : "l"(a), "l"(b), "l"(c)); return d;
}

// ---------------- transform builder ------------------------------------------
__device__ __forceinline__ void make_tf(const float* quat, const float* tra, int p, float tf[12]) {
    float a = quat[4*p], b = quat[4*p+1], c = quat[4*p+2], d = quat[4*p+3];
    float inv = rsqrtf(a*a + b*b + c*c + d*d);
    a *= inv; b *= inv; c *= inv; d *= inv;
    tf[0] = 1.f - 2.f*(c*c + d*d); tf[1] = 2.f*(b*c - a*d);        tf[2]  = 2.f*(a*c + b*d);        tf[3]  = tra[3*p+0];
    tf[4] = 2.f*(b*c + a*d);       tf[5] = 1.f - 2.f*(b*b + d*d);  tf[6]  = 2.f*(c*d - a*b);        tf[7]  = tra[3*p+1];
    tf[8] = 2.f*(b*d - a*c);       tf[9] = 2.f*(a*b + c*d);        tf[10] = 1.f - 2.f*(b*b + c*c);  tf[11] = tra[3*p+2];
}

// ---------------- launch 0: transforms + point buffers + minbuf -------------
__global__ void k_prep(const float* __restrict__ cad, const float* __restrict__ cam,
                       const float* __restrict__ quat, const float* __restrict__ tra,
                       float* __restrict__ out, int P, int M, int N, int total, int write_out) {
    int idx = blockIdx.x * blockDim.x + threadIdx.x;
    if (idx == 0) g_done = 0u;
    if (blockIdx.x == 0 && threadIdx.x < P && write_out) {
        float tf[12]; make_tf(quat, tra, threadIdx.x, tf);
        float* o = out + 1 + threadIdx.x * 16;
#pragma unroll
        for (int i = 0; i < 12; i++) o[i] = tf[i];
        o[12] = 0.f; o[13] = 0.f; o[14] = 0.f; o[15] = 1.f;
    }
    if (idx >= total) return;
    g_minbuf[idx] = 0x7f800000u;  // +inf

    float vx, vy, vz;
    if (idx < P * M) {
        int p = idx / M;
        float tf[12]; make_tf(quat, tra, p, tf);
        const float* pt = cad + (size_t)idx * 3;
        float x = pt[0], y = pt[1], z = pt[2];
        vx = tf[0]*x + tf[1]*y + tf[2]*z  + tf[3];
        vy = tf[4]*x + tf[5]*y + tf[6]*z  + tf[7];
        vz = tf[8]*x + tf[9]*y + tf[10]*z + tf[11];
        float n2 = vx*vx + vy*vy + vz*vz;
        float* T = g_cadT + (size_t)idx * 8;
        T[0] = vx; T[1] = vx; T[2] = vy; T[3] = vy;
        T[4] = vz; T[5] = vz; T[6] = 0.5f * n2; T[7] = 0.5f * n2;
        g_cadQ[idx] = make_float4(vx, vy, vz, n2);
    } else {
        int j = idx - P * M;
        const float* pt = cam + (size_t)j * 3;
        vx = pt[0]; vy = pt[1]; vz = pt[2];
        float n2 = vx*vx + vy*vy + vz*vz;
        float* T = g_camT + (size_t)j * 8;
        T[0] = vx; T[1] = vx; T[2] = vy; T[3] = vy;
        T[4] = vz; T[5] = vz; T[6] = 0.5f * n2; T[7] = 0.5f * n2;
        g_camQ[j] = make_float4(vx, vy, vz, n2);
    }
}

// ---------------- launch 1 (hot): chamfer, one item per block, occ 4 --------
__global__ void __launch_bounds__(256, 4) k_chamfer(int P, int M, int N,
                                                    int qcA, int tsA, int qcB, int tsB) {
    __shared__ __align__(16) float tile[TSL * 8];

    const int tid = threadIdx.x;
    const float INF = __int_as_float(0x7f800000);
    const int itemsA = P * qcA * tsA;
    const int item = blockIdx.x;

    int p, qc, sl, minoff;
    const float4* Q;
    const float*  T;
    if (item < itemsA) {
        p = item / (qcA * tsA); int r = item % (qcA * tsA); qc = r / tsA; sl = r % tsA;
        Q = g_cadQ + (size_t)p * M;
        T = g_camT + (size_t)p * N * 8;
        minoff = p * M;
    } else {
        int b1 = item - itemsA;
        p = b1 / (qcB * tsB); int r = b1 % (qcB * tsB); qc = r / tsB; sl = r % tsB;
        Q = g_camQ + (size_t)p * N;
        T = g_cadT + (size_t)p * M * 8;
        minoff = P * M + p * N;
    }

    // ---- cooperative tile load: 256 float4 = full 4KB ----
    ((float4*)tile)[tid] = ((const float4*)(T + (size_t)sl * TSL * 8))[tid];

    // ---- 4 query points per thread (2 packed pairs); no bounds checks ----
    u64 qnx[2], qny[2], qnz[2];
    float mn0[2], mn1[2], x2a[2], x2b[2];
    int base = qc * QCH + tid;
#pragma unroll
    for (int k = 0; k < 2; k++) {
        float4 A = Q[base + (2 * k) * 256];
        float4 B = Q[base + (2 * k + 1) * 256];
        qnx[k] = pack2(-A.x, -B.x);
        qny[k] = pack2(-A.y, -B.y);
        qnz[k] = pack2(-A.z, -B.z);
        x2a[k] = A.w; x2b[k] = B.w;
        mn0[k] = INF; mn1[k] = INF;
    }
    __syncthreads();

    // ---- main loop: 4 targets x 4 queries per iteration ----
#pragma unroll 2
    for (int j = 0; j < TSL; j += 4) {
        const float* tp = tile + j * 8;
        ulonglong2 a0 = *(const ulonglong2*)(tp);
        ulonglong2 a1 = *(const ulonglong2*)(tp + 4);
        ulonglong2 b0 = *(const ulonglong2*)(tp + 8);
        ulonglong2 b1 = *(const ulonglong2*)(tp + 12);
        ulonglong2 c0 = *(const ulonglong2*)(tp + 16);
        ulonglong2 c1 = *(const ulonglong2*)(tp + 20);
        ulonglong2 d0 = *(const ulonglong2*)(tp + 24);
        ulonglong2 d1 = *(const ulonglong2*)(tp + 28);
#pragma unroll
        for (int k = 0; k < 2; k++) {
            u64 gA = fma2(qnx[k], a0.x, a1.y);
            u64 gB = fma2(qnx[k], b0.x, b1.y);
            u64 gC = fma2(qnx[k], c0.x, c1.y);
            u64 gD = fma2(qnx[k], d0.x, d1.y);
            gA = fma2(qny[k], a0.y, gA);
            gB = fma2(qny[k], b0.y, gB);
            gC = fma2(qny[k], c0.y, gC);
            gD = fma2(qny[k], d0.y, gD);
            gA = fma2(qnz[k], a1.x, gA);
            gB = fma2(qnz[k], b1.x, gB);
            gC = fma2(qnz[k], c1.x, gC);
            gD = fma2(qnz[k], d1.x, gD);
            float alo, ahi, blo, bhi, clo, chi, dlo, dhi;
            unpack2(gA, alo, ahi); unpack2(gB, blo, bhi);
            unpack2(gC, clo, chi); unpack2(gD, dlo, dhi);
            float lo01 = fminf(alo, blo), lo23 = fminf(clo, dlo);
            float hi01 = fminf(ahi, bhi), hi23 = fminf(chi, dhi);
            mn0[k] = fminf(mn0[k], fminf(lo01, lo23));
            mn1[k] = fminf(mn1[k], fminf(hi01, hi23));
        }
    }

    // ---- combine across slices: d2 = 2*g + |q|^2 (>=0), bitwise uint min ----
#pragma unroll
    for (int k = 0; k < 2; k++) {
        float da = fmaxf(fmaf(2.f, mn0[k], x2a[k]), 0.f);
        float db = fmaxf(fmaf(2.f, mn1[k], x2b[k]), 0.f);
        atomicMin(g_minbuf + minoff + base + (2 * k) * 256,     __float_as_uint(da));
        atomicMin(g_minbuf + minoff + base + (2 * k + 1) * 256, __float_as_uint(db));
    }
}

// ---------------- launch 2: weighted sqrt-sum + fused final (last block) ----
__global__ void k_red(const float* __restrict__ w, float* __restrict__ out,
                      int P, int M, int N) {
    __shared__ float sh[256];
    __shared__ bool last;
    int total = P * (M + N);
    float s = 0.f;
    for (int e = blockIdx.x * 256 + threadIdx.x; e < total; e += NRED * 256) {
        int p; float invc;
        if (e < P * M) { p = e / M; invc = 1.0f / (float)M; }
        else           { p = (e - P * M) / N; invc = 1.0f / (float)N; }
        s += w[p] * invc * sqrtf(__uint_as_float(g_minbuf[e]));
    }
    sh[threadIdx.x] = s;
    __syncthreads();
    for (int o = 128; o > 0; o >>= 1) {
        if (threadIdx.x < o) sh[threadIdx.x] += sh[threadIdx.x + o];
        __syncthreads();
    }
    if (threadIdx.x == 0) {
        g_partial[blockIdx.x] = sh[0];
        __threadfence();
        last = (atomicAdd(&g_done, 1u) == NRED - 1);
    }
    __syncthreads();
    if (last) {   // final deterministic tree over 128 partials
        float v = (threadIdx.x < NRED) ? g_partial[threadIdx.x] : 0.f;
        sh[threadIdx.x] = v;
        __syncthreads();
        for (int o = 128; o > 0; o >>= 1) {
            if (threadIdx.x < o) sh[threadIdx.x] += sh[threadIdx.x + o];
            __syncthreads();
        }
        if (threadIdx.x == 0) out[0] = sh[0];
    }
}

// ---------------- launcher ----------------------------------------------------
extern "C" void kernel_launch(void* const* d_in, const int* in_sizes, int n_in,
                              void* d_out, int out_size) {
    const float* cam  = (const float*)d_in[0];  // (P,N,3)
    const float* cad  = (const float*)d_in[1];  // (P,M,3)
    const float* wgt  = (const float*)d_in[2];  // (P,)
    const float* quat = (const float*)d_in[3];  // (P,4)
    const float* tra  = (const float*)d_in[4];  // (P,3,1)
    float* out = (float*)d_out;

    int P = in_sizes[2];
    int N = in_sizes[0] / (3 * P);
    int M = in_sizes[1] / (3 * P);
    int write_out = (out_size >= 1 + 16 * P) ? 1 : 0;

    int total = P * (M + N);
    k_prep<<<(total + 255) / 256, 256>>>(cad, cam, quat, tra, out, P, M, N, total, write_out); // 0

    int qcA = (M + QCH - 1) / QCH, tsA = (N + TSL - 1) / TSL;
    int qcB = (N + QCH - 1) / QCH, tsB = (M + TSL - 1) / TSL;
    int items = P * (qcA * tsA + qcB * tsB);   // 4096
    k_chamfer<<<items, 256>>>(P, M, N, qcA, tsA, qcB, tsB);                                    // 1 (hot)

    k_red<<<NRED, 256>>>(wgt, out, P, M, N);                                                   // 2
}